// round 1
// baseline (speedup 1.0000x reference)
#include <cuda_runtime.h>
#include <cuda_fp16.h>
#include <cstdint>
#include <cstddef>

#define TOK 64
#define NF 8192
#define MF 8192
#define SPLITS 8
#define MTILE 128
#define KTILE 128
#define KSPLIT (NF / SPLITS)   /* 1024 */
#define WPAD 136               /* 128 + 8 halves padding */
#define XPAD 136

// Scratch (allocation-free rule: device globals)
__device__ __half g_xh[TOK * NF];                 // 1 MB  : FHT'd activations, fp16, [tok][k]
__device__ float  g_yp[(size_t)SPLITS * TOK * MF]; // 16 MB : split-K partials

__device__ __forceinline__ uint32_t smem_u32(const void* p) {
    return (uint32_t)__cvta_generic_to_shared(p);
}

// ---------------------------------------------------------------------------
// Kernel 1: x_rht = FHT(x * SV) -> fp16  (one CTA per token row)
// ---------------------------------------------------------------------------
__global__ void __launch_bounds__(1024) k_fht_x(const float* __restrict__ x,
                                                const float* __restrict__ SV) {
    __shared__ float s[NF];
    const int row = blockIdx.x, t = threadIdx.x;
    for (int i = t; i < NF; i += 1024) s[i] = x[row * NF + i] * SV[i];
    __syncthreads();
    for (int h = 1; h < NF; h <<= 1) {
        for (int p = t; p < NF / 2; p += 1024) {
            int i = ((p & ~(h - 1)) << 1) | (p & (h - 1));
            float a = s[i], b = s[i + h];
            s[i] = a + b; s[i + h] = a - b;
        }
        __syncthreads();
    }
    const float sc = 0.011048543456039806f;  // 1/sqrt(8192)
    __half2* dst = (__half2*)(g_xh + (size_t)row * NF);
    for (int i = t; i < NF / 2; i += 1024)
        dst[i] = __floats2half2_rn(s[2 * i] * sc, s[2 * i + 1] * sc);
}

// ---------------------------------------------------------------------------
// Kernel 2: fused dequant + GEMM (split-K partials)
//   grid = (MF/MTILE, SPLITS), block = 256 (8 warps)
//   warp w computes m rows [w*16, w*16+16) x all 64 tokens
// ---------------------------------------------------------------------------
__global__ void __launch_bounds__(256) k_gemm(const int*   __restrict__ Qidxs,
                                              const int*   __restrict__ Qidxs2,
                                              const float* __restrict__ cb1g,
                                              const float* __restrict__ cb2g,
                                              const float* __restrict__ irs_p) {
    extern __shared__ char smem[];
    float4* cb1 = (float4*)smem;          // 256 rows x 32B = 8 KB
    float4* cb2 = cb1 + 512;              // 8 KB (pre-scaled by irs)
    __half* ws  = (__half*)(smem + 16384);          // [128][WPAD]
    __half* xs  = ws + MTILE * WPAD;                // [64][XPAD]

    const int t = threadIdx.x;
    const int m0 = blockIdx.x * MTILE;
    const int split = blockIdx.y;
    const int lane = t & 31, w = t >> 5;
    const int r = t >> 1, gh = t & 1;   // decode: 2 threads per weight row

    // load codebooks to smem (cb2 pre-scaled by inv_resid_scale)
    {
        const float irs = irs_p[0];
        cb1[t]       = ((const float4*)cb1g)[t];
        cb1[t + 256] = ((const float4*)cb1g)[t + 256];
        float4 c = ((const float4*)cb2g)[t];
        c.x *= irs; c.y *= irs; c.z *= irs; c.w *= irs;
        cb2[t] = c;
        c = ((const float4*)cb2g)[t + 256];
        c.x *= irs; c.y *= irs; c.z *= irs; c.w *= irs;
        cb2[t + 256] = c;
    }

    float acc[8][4];
    #pragma unroll
    for (int i = 0; i < 8; ++i)
        #pragma unroll
        for (int j = 0; j < 4; ++j) acc[i][j] = 0.f;

    __syncthreads();

    for (int kc = 0; kc < KSPLIT / KTILE; ++kc) {     // 8 chunks of 128
        const int k0 = split * KSPLIT + kc * KTILE;
        const int gbase = k0 >> 3;                    // 16 groups per chunk

        // ---- load x tile: [64 tok][128 k] fp16 (padded rows) ----
        #pragma unroll
        for (int i = 0; i < 4; ++i) {
            int idx = t + 256 * i;                    // 0..1023
            int tok = idx >> 4, seg = idx & 15;
            uint4 v = *(const uint4*)(g_xh + (size_t)tok * NF + k0 + seg * 8);
            *(uint4*)(xs + tok * XPAD + seg * 8) = v;
        }

        // ---- decode W tile: gather fp32 codebook rows, convert to fp16 ----
        const int4* q1p = (const int4*)(Qidxs  + (size_t)(m0 + r) * 1024 + gbase + gh * 8);
        const int4* q2p = (const int4*)(Qidxs2 + (size_t)(m0 + r) * 1024 + gbase + gh * 8);
        int4 qa = q1p[0], qb = q1p[1];
        int4 qc = q2p[0], qd = q2p[1];
        int q1[8] = {qa.x, qa.y, qa.z, qa.w, qb.x, qb.y, qb.z, qb.w};
        int q2[8] = {qc.x, qc.y, qc.z, qc.w, qd.x, qd.y, qd.z, qd.w};
        __half* wrow = ws + r * WPAD + gh * 64;
        #pragma unroll
        for (int j = 0; j < 8; ++j) {
            float4 lo = cb1[q1[j] * 2], hi = cb1[q1[j] * 2 + 1];
            float4 l2 = cb2[q2[j] * 2], h2 = cb2[q2[j] * 2 + 1];
            union { uint4 u; __half2 h[4]; } pk;
            pk.h[0] = __floats2half2_rn(lo.x + l2.x, lo.y + l2.y);
            pk.h[1] = __floats2half2_rn(lo.z + l2.z, lo.w + l2.w);
            pk.h[2] = __floats2half2_rn(hi.x + h2.x, hi.y + h2.y);
            pk.h[3] = __floats2half2_rn(hi.z + h2.z, hi.w + h2.w);
            *(uint4*)(wrow + j * 8) = pk.u;
        }
        __syncthreads();

        // ---- MMA: A = W tile (m x k), B = x tile (k x n, n = tokens) ----
        #pragma unroll
        for (int kk = 0; kk < 8; ++kk) {
            uint32_t a0, a1, a2, a3;
            uint32_t aaddr = smem_u32(ws + (w * 16 + (lane & 15)) * WPAD
                                      + kk * 16 + (lane >> 4) * 8);
            asm volatile("ldmatrix.sync.aligned.m8n8.x4.shared.b16 {%0,%1,%2,%3}, [%4];"
                         : "=r"(a0), "=r"(a1), "=r"(a2), "=r"(a3) : "r"(aaddr));
            #pragma unroll
            for (int nt = 0; nt < 8; ++nt) {
                uint32_t b0, b1;
                uint32_t baddr = smem_u32(xs + (nt * 8 + (lane & 7)) * XPAD
                                          + kk * 16 + ((lane >> 3) & 1) * 8);
                asm volatile("ldmatrix.sync.aligned.m8n8.x2.shared.b16 {%0,%1}, [%2];"
                             : "=r"(b0), "=r"(b1) : "r"(baddr));
                asm volatile("mma.sync.aligned.m16n8k16.row.col.f32.f16.f16.f32 "
                             "{%0,%1,%2,%3}, {%4,%5,%6,%7}, {%8,%9}, {%0,%1,%2,%3};"
                             : "+f"(acc[nt][0]), "+f"(acc[nt][1]),
                               "+f"(acc[nt][2]), "+f"(acc[nt][3])
                             : "r"(a0), "r"(a1), "r"(a2), "r"(a3), "r"(b0), "r"(b1));
            }
        }
        __syncthreads();
    }

    // ---- epilogue: smem transpose -> coalesced partial store [tok][m] ----
    float* ob = (float*)smem;   // [64 tok][128 m] = 32 KB (codebooks dead now)
    #pragma unroll
    for (int nt = 0; nt < 8; ++nt) {
        int c0 = nt * 8 + (lane & 3) * 2;   // token
        int mr = w * 16 + (lane >> 2);      // local m row
        ob[c0 * 128 + mr]           = acc[nt][0];
        ob[(c0 + 1) * 128 + mr]     = acc[nt][1];
        ob[c0 * 128 + mr + 8]       = acc[nt][2];
        ob[(c0 + 1) * 128 + mr + 8] = acc[nt][3];
    }
    __syncthreads();
    float* dst = g_yp + (size_t)split * TOK * MF;
    #pragma unroll
    for (int i = 0; i < 8; ++i) {
        int idx = t + 256 * i;              // 0..2047 float4s
        int tok = idx >> 5, seg = idx & 31;
        float4 v = ((float4*)ob)[tok * 32 + seg];
        *(float4*)(dst + (size_t)tok * MF + m0 + seg * 4) = v;
    }
}

// ---------------------------------------------------------------------------
// Kernel 3: reduce splits, FHT along m, apply Wscale & SU, fp32 out
// ---------------------------------------------------------------------------
__global__ void __launch_bounds__(1024) k_final(float* __restrict__ out,
                                                const float* __restrict__ SU,
                                                const float* __restrict__ wsc_p) {
    __shared__ float s[MF];
    const int row = blockIdx.x, t = threadIdx.x;
    for (int m = t; m < MF; m += 1024) {
        float a = 0.f;
        #pragma unroll
        for (int sp = 0; sp < SPLITS; ++sp)
            a += g_yp[((size_t)sp * TOK + row) * MF + m];
        s[m] = a;
    }
    __syncthreads();
    for (int h = 1; h < MF; h <<= 1) {
        for (int p = t; p < MF / 2; p += 1024) {
            int i = ((p & ~(h - 1)) << 1) | (p & (h - 1));
            float a = s[i], b = s[i + h];
            s[i] = a + b; s[i + h] = a - b;
        }
        __syncthreads();
    }
    const float sc = wsc_p[0] * 0.011048543456039806f;  // Wscale / sqrt(8192)
    for (int m = t; m < MF; m += 1024)
        out[(size_t)row * MF + m] = s[m] * sc * SU[m];
}

// ---------------------------------------------------------------------------
extern "C" void kernel_launch(void* const* d_in, const int* in_sizes, int n_in,
                              void* d_out, int out_size) {
    const float* x      = (const float*)d_in[0];
    const int*   Qidxs  = (const int*)  d_in[1];
    const int*   Qidxs2 = (const int*)  d_in[2];
    const float* cb1    = (const float*)d_in[3];
    const float* cb2    = (const float*)d_in[4];
    const float* SU     = (const float*)d_in[5];
    const float* SV     = (const float*)d_in[6];
    const float* Wsc    = (const float*)d_in[7];
    const float* irs    = (const float*)d_in[8];
    float* out = (float*)d_out;

    const int SMEM_BYTES = 16384 + MTILE * WPAD * 2 + TOK * XPAD * 2;  // 68608
    cudaFuncSetAttribute(k_gemm, cudaFuncAttributeMaxDynamicSharedMemorySize, SMEM_BYTES);

    k_fht_x<<<TOK, 1024>>>(x, SV);
    k_gemm<<<dim3(MF / MTILE, SPLITS), 256, SMEM_BYTES>>>(Qidxs, Qidxs2, cb1, cb2, irs);
    k_final<<<TOK, 1024>>>(out, SU, Wsc);
}

// round 4
// speedup vs baseline: 1.4816x; 1.4816x over previous
#include <cuda_runtime.h>
#include <cuda_fp16.h>
#include <cstdint>
#include <cstddef>

#define TOK 64
#define NF 8192
#define MF 8192
#define SPLITS 8
#define KSPLIT 1024
#define KTILE 128
#define CHUNKS 8
#define MTILE 128
#define WPAD 136           /* halves per W row (128 + 8 pad) */
#define XPAD 136

// ---- scratch (allocation-free rule: device globals) ----
__device__ __half g_xh[TOK * NF];                  // 1 MB  FHT'd activations fp16 [tok][k]
__device__ float  g_yp[(size_t)SPLITS * TOK * MF]; // 16 MB split-K partials

// ---- k_gemm dynamic smem layout ----
#define OFF_CB1  0                       /* fp16 codebook1: 256 x 16B = 4 KB   */
#define OFF_CB2  4096                    /* fp16 codebook2 (pre-scaled): 4 KB  */
#define OFF_W0   8192                    /* W buf0: 128*WPAD*2 = 34816 B       */
#define OFF_W1   (OFF_W0 + 34816)
#define OFF_X0   (OFF_W1 + 34816)        /* X buf0: 64*XPAD*2 = 17408 B        */
#define OFF_X1   (OFF_X0 + 17408)
#define SMEM_SZ  (OFF_X1 + 17408)        /* 112640 B -> 2 CTAs/SM              */
#define OBPAD 132                        /* epilogue fp32 row stride           */

__device__ __forceinline__ uint32_t smem_u32(const void* p) {
    return (uint32_t)__cvta_generic_to_shared(p);
}

// ---------------------------------------------------------------------------
// register FHT helpers
// ---------------------------------------------------------------------------
template <int N>
__device__ __forceinline__ void fht_regs(float* v) {
    #pragma unroll
    for (int h = 1; h < N; h <<= 1)
        #pragma unroll
        for (int i = 0; i < N; ++i)
            if ((i & h) == 0) { float a = v[i], b = v[i + h]; v[i] = a + b; v[i + h] = a - b; }
}
__device__ __forceinline__ int pad(int i) { return i + (i >> 5); }

// ---------------------------------------------------------------------------
// Kernel 1: x_rht = FHT(x * SV) -> fp16   (register radix, 4 smem rounds)
// ---------------------------------------------------------------------------
__global__ void __launch_bounds__(1024) k_fht_x(const float* __restrict__ x,
                                                const float* __restrict__ SV) {
    __shared__ float s[NF + NF / 32];
    const int row = blockIdx.x, t = threadIdx.x;
    float v[16];
    {   // R1: contiguous 8, stages h=1,2,4
        const float4* xp = (const float4*)(x + (size_t)row * NF + t * 8);
        const float4* sp = (const float4*)(SV + t * 8);
        float4 a0 = xp[0], a1 = xp[1], b0 = sp[0], b1 = sp[1];
        v[0] = a0.x * b0.x; v[1] = a0.y * b0.y; v[2] = a0.z * b0.z; v[3] = a0.w * b0.w;
        v[4] = a1.x * b1.x; v[5] = a1.y * b1.y; v[6] = a1.z * b1.z; v[7] = a1.w * b1.w;
        fht_regs<8>(v);
        int base = t * 8;
        #pragma unroll
        for (int j = 0; j < 8; ++j) s[pad(base + j)] = v[j];
    }
    __syncthreads();
    {   // R2: stride 8, stages h=8,16,32
        int base = ((t >> 3) << 6) + (t & 7);
        #pragma unroll
        for (int j = 0; j < 8; ++j) v[j] = s[pad(base + (j << 3))];
        fht_regs<8>(v);
        #pragma unroll
        for (int j = 0; j < 8; ++j) s[pad(base + (j << 3))] = v[j];
    }
    __syncthreads();
    {   // R3: stride 64, stages h=64,128,256
        int base = ((t >> 6) << 9) + (t & 63);
        #pragma unroll
        for (int j = 0; j < 8; ++j) v[j] = s[pad(base + (j << 6))];
        fht_regs<8>(v);
        #pragma unroll
        for (int j = 0; j < 8; ++j) s[pad(base + (j << 6))] = v[j];
    }
    __syncthreads();
    if (t < 512) {  // R4: stride 512, radix-16, stages h=512..4096
        #pragma unroll
        for (int j = 0; j < 16; ++j) v[j] = s[pad(t + (j << 9))];
        fht_regs<16>(v);
        #pragma unroll
        for (int j = 0; j < 16; ++j) s[pad(t + (j << 9))] = v[j];
    }
    __syncthreads();
    const float sc = 0.011048543456039806f;  // 1/sqrt(8192)
    __half2* dst = (__half2*)(g_xh + (size_t)row * NF);
    for (int i = t; i < NF / 2; i += 1024)
        dst[i] = __floats2half2_rn(s[pad(2 * i)] * sc, s[pad(2 * i + 1)] * sc);
}

// ---------------------------------------------------------------------------
// Kernel 2: fused dequant + HMMA GEMM, software-pipelined, 1 barrier/chunk
//   grid = (MF/MTILE, SPLITS), 256 threads, warp tile 32m x 32n
// ---------------------------------------------------------------------------
__global__ void __launch_bounds__(256, 2) k_gemm(const int*   __restrict__ Qidxs,
                                                 const int*   __restrict__ Qidxs2,
                                                 const float* __restrict__ cb1g,
                                                 const float* __restrict__ cb2g,
                                                 const float* __restrict__ irs_p) {
    extern __shared__ char smem[];
    const int t = threadIdx.x, w = t >> 5, lane = t & 31;
    const int m0 = blockIdx.x * MTILE, split = blockIdx.y;
    const int mw = w & 3, nw = w >> 2;
    const int r = t >> 1, gh = t & 1;               // decode row / half assignment

    // ---- fp16 codebooks (cb2 pre-scaled by inv_resid_scale) ----
    {
        const float irs = irs_p[0];
        const float4* p1 = (const float4*)(cb1g + t * 8);
        const float4* p2 = (const float4*)(cb2g + t * 8);
        float4 a0 = p1[0], a1 = p1[1], b0 = p2[0], b1 = p2[1];
        union { uint4 u; __half2 h[4]; } pk;
        pk.h[0] = __floats2half2_rn(a0.x, a0.y); pk.h[1] = __floats2half2_rn(a0.z, a0.w);
        pk.h[2] = __floats2half2_rn(a1.x, a1.y); pk.h[3] = __floats2half2_rn(a1.z, a1.w);
        ((uint4*)(smem + OFF_CB1))[t] = pk.u;
        pk.h[0] = __floats2half2_rn(b0.x * irs, b0.y * irs);
        pk.h[1] = __floats2half2_rn(b0.z * irs, b0.w * irs);
        pk.h[2] = __floats2half2_rn(b1.x * irs, b1.y * irs);
        pk.h[3] = __floats2half2_rn(b1.z * irs, b1.w * irs);
        ((uint4*)(smem + OFF_CB2))[t] = pk.u;
    }
    // Codebooks are read by ALL threads in decode (cross-thread gather):
    // must be visible before the prologue decode below. (R3 bug: missing.)
    __syncthreads();

    const uint4* cb1 = (const uint4*)(smem + OFF_CB1);
    const uint4* cb2 = (const uint4*)(smem + OFF_CB2);
    const int* q1base = Qidxs  + (size_t)(m0 + r) * (NF / 8) + gh * 8;
    const int* q2base = Qidxs2 + (size_t)(m0 + r) * (NF / 8) + gh * 8;

    float acc[2][4][4];
    #pragma unroll
    for (int a = 0; a < 2; ++a)
        #pragma unroll
        for (int b = 0; b < 4; ++b)
            #pragma unroll
            for (int c = 0; c < 4; ++c) acc[a][b][c] = 0.f;

    int4 q1a, q1b, q2a, q2b;      // prefetched indices (8+8 groups halves)
    uint4 xv[4];                  // prefetched X rows

    auto decode_store = [&](char* wb) {
        int q1[8] = {q1a.x, q1a.y, q1a.z, q1a.w, q1b.x, q1b.y, q1b.z, q1b.w};
        int q2[8] = {q2a.x, q2a.y, q2a.z, q2a.w, q2b.x, q2b.y, q2b.z, q2b.w};
        __half* wrow = (__half*)wb + r * WPAD + gh * 64;
        #pragma unroll
        for (int j = 0; j < 8; ++j) {
            uint4 c1 = cb1[q1[j]], c2 = cb2[q2[j]];
            __half2* h1 = (__half2*)&c1;
            const __half2* h2 = (const __half2*)&c2;
            h1[0] = __hadd2(h1[0], h2[0]); h1[1] = __hadd2(h1[1], h2[1]);
            h1[2] = __hadd2(h1[2], h2[2]); h1[3] = __hadd2(h1[3], h2[3]);
            *(uint4*)(wrow + j * 8) = c1;
        }
    };
    auto x_store = [&](char* xb) {
        #pragma unroll
        for (int i = 0; i < 4; ++i) {
            int idx = t + 256 * i, tok = idx >> 4, seg = idx & 15;
            *(uint4*)((__half*)xb + tok * XPAD + seg * 8) = xv[i];
        }
    };
    auto prefetch = [&](int k0) {
        int gb = k0 >> 3;
        q1a = *(const int4*)(q1base + gb); q1b = *(const int4*)(q1base + gb + 4);
        q2a = *(const int4*)(q2base + gb); q2b = *(const int4*)(q2base + gb + 4);
        #pragma unroll
        for (int i = 0; i < 4; ++i) {
            int idx = t + 256 * i, tok = idx >> 4, seg = idx & 15;
            xv[i] = *(const uint4*)(g_xh + (size_t)tok * NF + k0 + seg * 8);
        }
    };

    // ---- prologue: chunk 0 into buffer 0 ----
    prefetch(split * KSPLIT);
    x_store(smem + OFF_X0);
    decode_store(smem + OFF_W0);
    __syncthreads();

    for (int c = 0; c < CHUNKS; ++c) {
        const int b = c & 1;
        if (c < CHUNKS - 1) prefetch(split * KSPLIT + (c + 1) * KTILE);

        // ---- MMA on buffer b ----
        const __half* ws = (const __half*)(smem + (b ? OFF_W1 : OFF_W0));
        const __half* xs = (const __half*)(smem + (b ? OFF_X1 : OFF_X0));
        #pragma unroll
        for (int kk = 0; kk < 8; ++kk) {
            uint32_t A[2][4], B[4][2];
            #pragma unroll
            for (int mi = 0; mi < 2; ++mi) {
                uint32_t ad = smem_u32(ws + (mw * 32 + mi * 16 + (lane & 15)) * WPAD
                                       + kk * 16 + (lane >> 4) * 8);
                asm volatile("ldmatrix.sync.aligned.m8n8.x4.shared.b16 {%0,%1,%2,%3}, [%4];"
                             : "=r"(A[mi][0]), "=r"(A[mi][1]), "=r"(A[mi][2]), "=r"(A[mi][3])
                             : "r"(ad));
            }
            #pragma unroll
            for (int ni = 0; ni < 4; ++ni) {
                uint32_t bd = smem_u32(xs + (nw * 32 + ni * 8 + (lane & 7)) * XPAD
                                       + kk * 16 + ((lane >> 3) & 1) * 8);
                asm volatile("ldmatrix.sync.aligned.m8n8.x2.shared.b16 {%0,%1}, [%2];"
                             : "=r"(B[ni][0]), "=r"(B[ni][1]) : "r"(bd));
            }
            #pragma unroll
            for (int mi = 0; mi < 2; ++mi)
                #pragma unroll
                for (int ni = 0; ni < 4; ++ni)
                    asm volatile("mma.sync.aligned.m16n8k16.row.col.f32.f16.f16.f32 "
                                 "{%0,%1,%2,%3}, {%4,%5,%6,%7}, {%8,%9}, {%0,%1,%2,%3};"
                                 : "+f"(acc[mi][ni][0]), "+f"(acc[mi][ni][1]),
                                   "+f"(acc[mi][ni][2]), "+f"(acc[mi][ni][3])
                                 : "r"(A[mi][0]), "r"(A[mi][1]), "r"(A[mi][2]), "r"(A[mi][3]),
                                   "r"(B[ni][0]), "r"(B[ni][1]));
        }

        // ---- decode next chunk into the other buffer ----
        if (c < CHUNKS - 1) {
            x_store(smem + (b ? OFF_X0 : OFF_X1));
            decode_store(smem + (b ? OFF_W0 : OFF_W1));
        }
        __syncthreads();
    }

    // ---- epilogue: regs -> smem transpose [tok][m] -> coalesced partials ----
    float* ob = (float*)(smem + OFF_W0);    // 64 * OBPAD * 4 = 33792 B
    #pragma unroll
    for (int mi = 0; mi < 2; ++mi)
        #pragma unroll
        for (int ni = 0; ni < 4; ++ni) {
            int m = mw * 32 + mi * 16 + (lane >> 2);
            int n = nw * 32 + ni * 8 + (lane & 3) * 2;
            ob[n * OBPAD + m]           = acc[mi][ni][0];
            ob[(n + 1) * OBPAD + m]     = acc[mi][ni][1];
            ob[n * OBPAD + m + 8]       = acc[mi][ni][2];
            ob[(n + 1) * OBPAD + m + 8] = acc[mi][ni][3];
        }
    __syncthreads();
    float* dst = g_yp + (size_t)split * TOK * MF;
    #pragma unroll
    for (int i = 0; i < 8; ++i) {
        int idx = t + 256 * i, tok = idx >> 5, seg = idx & 31;
        float4 val = *(const float4*)(ob + tok * OBPAD + seg * 4);
        *(float4*)(dst + (size_t)tok * MF + m0 + seg * 4) = val;
    }
}

// ---------------------------------------------------------------------------
// Kernel 3: reduce splits, FHT along m, apply Wscale & SU
// ---------------------------------------------------------------------------
__global__ void __launch_bounds__(1024) k_final(float* __restrict__ out,
                                                const float* __restrict__ SU,
                                                const float* __restrict__ wsc_p) {
    __shared__ float s[MF + MF / 32];
    const int row = blockIdx.x, t = threadIdx.x;
    float v[16];
    {   // load + split reduction + R1
        float4 a0 = {0, 0, 0, 0}, a1 = {0, 0, 0, 0};
        #pragma unroll
        for (int sp = 0; sp < SPLITS; ++sp) {
            const float4* p = (const float4*)(g_yp + ((size_t)sp * TOK + row) * MF + t * 8);
            float4 x0 = p[0], x1 = p[1];
            a0.x += x0.x; a0.y += x0.y; a0.z += x0.z; a0.w += x0.w;
            a1.x += x1.x; a1.y += x1.y; a1.z += x1.z; a1.w += x1.w;
        }
        v[0] = a0.x; v[1] = a0.y; v[2] = a0.z; v[3] = a0.w;
        v[4] = a1.x; v[5] = a1.y; v[6] = a1.z; v[7] = a1.w;
        fht_regs<8>(v);
        int base = t * 8;
        #pragma unroll
        for (int j = 0; j < 8; ++j) s[pad(base + j)] = v[j];
    }
    __syncthreads();
    {
        int base = ((t >> 3) << 6) + (t & 7);
        #pragma unroll
        for (int j = 0; j < 8; ++j) v[j] = s[pad(base + (j << 3))];
        fht_regs<8>(v);
        #pragma unroll
        for (int j = 0; j < 8; ++j) s[pad(base + (j << 3))] = v[j];
    }
    __syncthreads();
    {
        int base = ((t >> 6) << 9) + (t & 63);
        #pragma unroll
        for (int j = 0; j < 8; ++j) v[j] = s[pad(base + (j << 6))];
        fht_regs<8>(v);
        #pragma unroll
        for (int j = 0; j < 8; ++j) s[pad(base + (j << 6))] = v[j];
    }
    __syncthreads();
    if (t < 512) {
        #pragma unroll
        for (int j = 0; j < 16; ++j) v[j] = s[pad(t + (j << 9))];
        fht_regs<16>(v);
        #pragma unroll
        for (int j = 0; j < 16; ++j) s[pad(t + (j << 9))] = v[j];
    }
    __syncthreads();
    const float sc = wsc_p[0] * 0.011048543456039806f;  // Wscale / sqrt(8192)
    for (int m = t; m < MF; m += 1024)
        out[(size_t)row * MF + m] = s[pad(m)] * sc * SU[m];
}

// ---------------------------------------------------------------------------
extern "C" void kernel_launch(void* const* d_in, const int* in_sizes, int n_in,
                              void* d_out, int out_size) {
    const float* x      = (const float*)d_in[0];
    const int*   Qidxs  = (const int*)  d_in[1];
    const int*   Qidxs2 = (const int*)  d_in[2];
    const float* cb1    = (const float*)d_in[3];
    const float* cb2    = (const float*)d_in[4];
    const float* SU     = (const float*)d_in[5];
    const float* SV     = (const float*)d_in[6];
    const float* Wsc    = (const float*)d_in[7];
    const float* irs    = (const float*)d_in[8];
    float* out = (float*)d_out;

    cudaFuncSetAttribute(k_gemm, cudaFuncAttributeMaxDynamicSharedMemorySize, SMEM_SZ);

    k_fht_x<<<TOK, 1024>>>(x, SV);
    k_gemm<<<dim3(MF / MTILE, SPLITS), 256, SMEM_SZ>>>(Qidxs, Qidxs2, cb1, cb2, irs);
    k_final<<<TOK, 1024>>>(out, SU, Wsc);
}

// round 5
// speedup vs baseline: 1.7778x; 1.1999x over previous
#include <cuda_runtime.h>
#include <cuda_fp16.h>
#include <cstdint>
#include <cstddef>

#define TOK 64
#define NF 8192
#define MF 8192
#define SPLITS 4
#define KSPLIT 2048        /* NF / SPLITS */
#define KTILE 128
#define CHUNKS 16          /* KSPLIT / KTILE */
#define MTILE 128
#define WPAD 136           /* halves per W row (128 + 8 pad) */
#define XPAD 136

// ---- scratch (allocation-free rule: device globals) ----
__device__ __half g_xh[TOK * NF];                  // 1 MB  FHT'd activations fp16 [tok][k]
__device__ float  g_yp[(size_t)SPLITS * TOK * MF]; // 8 MB split-K partials

// ---- k_gemm dynamic smem layout ----
#define OFF_CB1  0                       /* fp16 codebook1: 4 KB               */
#define OFF_CB2  4096                    /* fp16 codebook2 (pre-scaled): 4 KB  */
#define OFF_W0   8192                    /* W buf0: 128*WPAD*2 = 34816 B       */
#define OFF_W1   (OFF_W0 + 34816)
#define OFF_X0   (OFF_W1 + 34816)        /* X buf0: 64*XPAD*2 = 17408 B        */
#define OFF_X1   (OFF_X0 + 17408)
#define SMEM_SZ  (OFF_X1 + 17408)        /* 112640 B -> 2 CTAs/SM              */
#define OBPAD 132                        /* epilogue fp32 row stride           */

// named barriers: ready[b] = 1+b, consumed[b] = 3+b
#define BAR_READY(b)    (1 + (b))
#define BAR_CONSUMED(b) (3 + (b))

__device__ __forceinline__ uint32_t smem_u32(const void* p) {
    return (uint32_t)__cvta_generic_to_shared(p);
}
__device__ __forceinline__ void bar_sync(int id) {
    asm volatile("bar.sync %0, 256;" :: "r"(id) : "memory");
}
__device__ __forceinline__ void bar_arrive(int id) {
    asm volatile("bar.arrive %0, 256;" :: "r"(id) : "memory");
}
__device__ __forceinline__ void cp_async16(uint32_t dst, const void* src) {
    asm volatile("cp.async.cg.shared.global [%0], [%1], 16;" :: "r"(dst), "l"(src) : "memory");
}

// ---------------------------------------------------------------------------
// register FHT helpers
// ---------------------------------------------------------------------------
template <int N>
__device__ __forceinline__ void fht_regs(float* v) {
    #pragma unroll
    for (int h = 1; h < N; h <<= 1)
        #pragma unroll
        for (int i = 0; i < N; ++i)
            if ((i & h) == 0) { float a = v[i], b = v[i + h]; v[i] = a + b; v[i + h] = a - b; }
}
__device__ __forceinline__ int pad(int i) { return i + (i >> 5); }

// ---------------------------------------------------------------------------
// Kernel 1: x_rht = FHT(x * SV) -> fp16   (register radix, 4 smem rounds)
// ---------------------------------------------------------------------------
__global__ void __launch_bounds__(1024) k_fht_x(const float* __restrict__ x,
                                                const float* __restrict__ SV) {
    __shared__ float s[NF + NF / 32];
    const int row = blockIdx.x, t = threadIdx.x;
    float v[16];
    {   // R1: contiguous 8, stages h=1,2,4
        const float4* xp = (const float4*)(x + (size_t)row * NF + t * 8);
        const float4* sp = (const float4*)(SV + t * 8);
        float4 a0 = xp[0], a1 = xp[1], b0 = sp[0], b1 = sp[1];
        v[0] = a0.x * b0.x; v[1] = a0.y * b0.y; v[2] = a0.z * b0.z; v[3] = a0.w * b0.w;
        v[4] = a1.x * b1.x; v[5] = a1.y * b1.y; v[6] = a1.z * b1.z; v[7] = a1.w * b1.w;
        fht_regs<8>(v);
        int base = t * 8;
        #pragma unroll
        for (int j = 0; j < 8; ++j) s[pad(base + j)] = v[j];
    }
    __syncthreads();
    {   // R2: stride 8
        int base = ((t >> 3) << 6) + (t & 7);
        #pragma unroll
        for (int j = 0; j < 8; ++j) v[j] = s[pad(base + (j << 3))];
        fht_regs<8>(v);
        #pragma unroll
        for (int j = 0; j < 8; ++j) s[pad(base + (j << 3))] = v[j];
    }
    __syncthreads();
    {   // R3: stride 64
        int base = ((t >> 6) << 9) + (t & 63);
        #pragma unroll
        for (int j = 0; j < 8; ++j) v[j] = s[pad(base + (j << 6))];
        fht_regs<8>(v);
        #pragma unroll
        for (int j = 0; j < 8; ++j) s[pad(base + (j << 6))] = v[j];
    }
    __syncthreads();
    if (t < 512) {  // R4: stride 512, radix-16
        #pragma unroll
        for (int j = 0; j < 16; ++j) v[j] = s[pad(t + (j << 9))];
        fht_regs<16>(v);
        #pragma unroll
        for (int j = 0; j < 16; ++j) s[pad(t + (j << 9))] = v[j];
    }
    __syncthreads();
    const float sc = 0.011048543456039806f;  // 1/sqrt(8192)
    __half2* dst = (__half2*)(g_xh + (size_t)row * NF);
    for (int i = t; i < NF / 2; i += 1024)
        dst[i] = __floats2half2_rn(s[pad(2 * i)] * sc, s[pad(2 * i + 1)] * sc);
}

// ---------------------------------------------------------------------------
// Kernel 2: warp-specialized dequant + HMMA GEMM
//   grid = (MF/MTILE, SPLITS), 256 threads
//   warps 0-3: consumers (MMA, warp tile 32m x 64n)
//   warps 4-7: producers (decode W + cp.async X)
// ---------------------------------------------------------------------------
__global__ void __launch_bounds__(256, 2) k_gemm(const int*   __restrict__ Qidxs,
                                                 const int*   __restrict__ Qidxs2,
                                                 const float* __restrict__ cb1g,
                                                 const float* __restrict__ cb2g,
                                                 const float* __restrict__ irs_p) {
    extern __shared__ char smem[];
    const int t = threadIdx.x, w = t >> 5, lane = t & 31;
    const int m0 = blockIdx.x * MTILE, split = blockIdx.y;
    const uint32_t sb = smem_u32(smem);

    // ---- fp16 codebooks (cb2 pre-scaled by inv_resid_scale) ----
    {
        const float irs = irs_p[0];
        const float4* p1 = (const float4*)(cb1g + t * 8);
        const float4* p2 = (const float4*)(cb2g + t * 8);
        float4 a0 = p1[0], a1 = p1[1], b0 = p2[0], b1 = p2[1];
        union { uint4 u; __half2 h[4]; } pk;
        pk.h[0] = __floats2half2_rn(a0.x, a0.y); pk.h[1] = __floats2half2_rn(a0.z, a0.w);
        pk.h[2] = __floats2half2_rn(a1.x, a1.y); pk.h[3] = __floats2half2_rn(a1.z, a1.w);
        ((uint4*)(smem + OFF_CB1))[t] = pk.u;
        pk.h[0] = __floats2half2_rn(b0.x * irs, b0.y * irs);
        pk.h[1] = __floats2half2_rn(b0.z * irs, b0.w * irs);
        pk.h[2] = __floats2half2_rn(b1.x * irs, b1.y * irs);
        pk.h[3] = __floats2half2_rn(b1.z * irs, b1.w * irs);
        ((uint4*)(smem + OFF_CB2))[t] = pk.u;
    }
    __syncthreads();   // codebooks visible to producer gathers

    float acc[2][8][4];   // consumer accumulators (32m x 64n)

    if (w < 4) {
        // ================= CONSUMER =================
        #pragma unroll
        for (int mi = 0; mi < 2; ++mi)
            #pragma unroll
            for (int nt = 0; nt < 8; ++nt)
                #pragma unroll
                for (int e = 0; e < 4; ++e) acc[mi][nt][e] = 0.f;

        for (int c = 0; c < CHUNKS; ++c) {
            const int b = c & 1;
            bar_sync(BAR_READY(b));
            const __half* ws = (const __half*)(smem + (b ? OFF_W1 : OFF_W0));
            const __half* xs = (const __half*)(smem + (b ? OFF_X1 : OFF_X0));
            #pragma unroll
            for (int kk = 0; kk < 8; ++kk) {
                uint32_t A[2][4], B[8][2];
                #pragma unroll
                for (int mi = 0; mi < 2; ++mi) {
                    uint32_t ad = smem_u32(ws + (w * 32 + mi * 16 + (lane & 15)) * WPAD
                                           + kk * 16 + (lane >> 4) * 8);
                    asm volatile("ldmatrix.sync.aligned.m8n8.x4.shared.b16 {%0,%1,%2,%3}, [%4];"
                                 : "=r"(A[mi][0]), "=r"(A[mi][1]), "=r"(A[mi][2]), "=r"(A[mi][3])
                                 : "r"(ad));
                }
                #pragma unroll
                for (int nt = 0; nt < 8; ++nt) {
                    uint32_t bd = smem_u32(xs + (nt * 8 + (lane & 7)) * XPAD
                                           + kk * 16 + ((lane >> 3) & 1) * 8);
                    asm volatile("ldmatrix.sync.aligned.m8n8.x2.shared.b16 {%0,%1}, [%2];"
                                 : "=r"(B[nt][0]), "=r"(B[nt][1]) : "r"(bd));
                }
                #pragma unroll
                for (int mi = 0; mi < 2; ++mi)
                    #pragma unroll
                    for (int nt = 0; nt < 8; ++nt)
                        asm volatile("mma.sync.aligned.m16n8k16.row.col.f32.f16.f16.f32 "
                                     "{%0,%1,%2,%3}, {%4,%5,%6,%7}, {%8,%9}, {%0,%1,%2,%3};"
                                     : "+f"(acc[mi][nt][0]), "+f"(acc[mi][nt][1]),
                                       "+f"(acc[mi][nt][2]), "+f"(acc[mi][nt][3])
                                     : "r"(A[mi][0]), "r"(A[mi][1]), "r"(A[mi][2]), "r"(A[mi][3]),
                                       "r"(B[nt][0]), "r"(B[nt][1]));
            }
            bar_arrive(BAR_CONSUMED(b));
        }
    } else {
        // ================= PRODUCER =================
        const int pt = t - 128;                  // 0..127 = W row within tile
        const uint4* cb1 = (const uint4*)(smem + OFF_CB1);
        const uint4* cb2 = (const uint4*)(smem + OFF_CB2);
        const int* q1base = Qidxs  + (size_t)(m0 + pt) * (NF / 8) + split * (KSPLIT / 8);
        const int* q2base = Qidxs2 + (size_t)(m0 + pt) * (NF / 8) + split * (KSPLIT / 8);

        int4 c1[4], c2[4], n1[4], n2[4];
        #pragma unroll
        for (int i = 0; i < 4; ++i) {            // prime chunk 0 indices
            c1[i] = *(const int4*)(q1base + i * 4);
            c2[i] = *(const int4*)(q2base + i * 4);
        }

        for (int c = 0; c < CHUNKS; ++c) {
            const int b = c & 1;
            if (c >= 2) bar_sync(BAR_CONSUMED(b));

            // stage X tile via cp.async (no reg round-trip)
            const int k0 = split * KSPLIT + c * KTILE;
            const uint32_t xb = sb + (b ? OFF_X1 : OFF_X0);
            #pragma unroll
            for (int i = 0; i < 8; ++i) {
                int idx = pt + 128 * i, tok = idx >> 4, seg = idx & 15;
                cp_async16(xb + (tok * XPAD + seg * 8) * 2,
                           g_xh + (size_t)tok * NF + k0 + seg * 8);
            }
            asm volatile("cp.async.commit_group;" ::: "memory");

            // prefetch next chunk's indices (hidden under decode below)
            if (c + 1 < CHUNKS) {
                #pragma unroll
                for (int i = 0; i < 4; ++i) {
                    n1[i] = *(const int4*)(q1base + (c + 1) * 16 + i * 4);
                    n2[i] = *(const int4*)(q2base + (c + 1) * 16 + i * 4);
                }
            }

            // decode this chunk's 16 groups for row pt
            {
                int q1[16] = {c1[0].x, c1[0].y, c1[0].z, c1[0].w,
                              c1[1].x, c1[1].y, c1[1].z, c1[1].w,
                              c1[2].x, c1[2].y, c1[2].z, c1[2].w,
                              c1[3].x, c1[3].y, c1[3].z, c1[3].w};
                int q2[16] = {c2[0].x, c2[0].y, c2[0].z, c2[0].w,
                              c2[1].x, c2[1].y, c2[1].z, c2[1].w,
                              c2[2].x, c2[2].y, c2[2].z, c2[2].w,
                              c2[3].x, c2[3].y, c2[3].z, c2[3].w};
                __half* wrow = (__half*)(smem + (b ? OFF_W1 : OFF_W0)) + pt * WPAD;
                #pragma unroll
                for (int j = 0; j < 16; ++j) {
                    uint4 v1 = cb1[q1[j]], v2 = cb2[q2[j]];
                    __half2* h1 = (__half2*)&v1;
                    const __half2* h2 = (const __half2*)&v2;
                    h1[0] = __hadd2(h1[0], h2[0]); h1[1] = __hadd2(h1[1], h2[1]);
                    h1[2] = __hadd2(h1[2], h2[2]); h1[3] = __hadd2(h1[3], h2[3]);
                    *(uint4*)(wrow + j * 8) = v1;
                }
            }

            asm volatile("cp.async.wait_group 0;" ::: "memory");
            bar_arrive(BAR_READY(b));

            #pragma unroll
            for (int i = 0; i < 4; ++i) { c1[i] = n1[i]; c2[i] = n2[i]; }
        }
    }

    // ---- epilogue: consumer regs -> smem transpose [tok][m] ----
    float* ob = (float*)(smem + OFF_W0);    // 64 * OBPAD * 4 = 33792 B
    if (w < 4) {
        #pragma unroll
        for (int mi = 0; mi < 2; ++mi)
            #pragma unroll
            for (int nt = 0; nt < 8; ++nt) {
                int m = w * 32 + mi * 16 + (lane >> 2);
                int n = nt * 8 + (lane & 3) * 2;
                ob[n * OBPAD + m]           = acc[mi][nt][0];
                ob[(n + 1) * OBPAD + m]     = acc[mi][nt][1];
                ob[n * OBPAD + m + 8]       = acc[mi][nt][2];
                ob[(n + 1) * OBPAD + m + 8] = acc[mi][nt][3];
            }
    }
    __syncthreads();
    float* dst = g_yp + (size_t)split * TOK * MF;
    #pragma unroll
    for (int i = 0; i < 8; ++i) {
        int idx = t + 256 * i, tok = idx >> 5, seg = idx & 31;
        float4 val = *(const float4*)(ob + tok * OBPAD + seg * 4);
        *(float4*)(dst + (size_t)tok * MF + m0 + seg * 4) = val;
    }
}

// ---------------------------------------------------------------------------
// Kernel 3: reduce splits, FHT along m, apply Wscale & SU
// ---------------------------------------------------------------------------
__global__ void __launch_bounds__(1024) k_final(float* __restrict__ out,
                                                const float* __restrict__ SU,
                                                const float* __restrict__ wsc_p) {
    __shared__ float s[MF + MF / 32];
    const int row = blockIdx.x, t = threadIdx.x;
    float v[16];
    {   // load + split reduction + R1
        float4 a0 = {0, 0, 0, 0}, a1 = {0, 0, 0, 0};
        #pragma unroll
        for (int sp = 0; sp < SPLITS; ++sp) {
            const float4* p = (const float4*)(g_yp + ((size_t)sp * TOK + row) * MF + t * 8);
            float4 x0 = p[0], x1 = p[1];
            a0.x += x0.x; a0.y += x0.y; a0.z += x0.z; a0.w += x0.w;
            a1.x += x1.x; a1.y += x1.y; a1.z += x1.z; a1.w += x1.w;
        }
        v[0] = a0.x; v[1] = a0.y; v[2] = a0.z; v[3] = a0.w;
        v[4] = a1.x; v[5] = a1.y; v[6] = a1.z; v[7] = a1.w;
        fht_regs<8>(v);
        int base = t * 8;
        #pragma unroll
        for (int j = 0; j < 8; ++j) s[pad(base + j)] = v[j];
    }
    __syncthreads();
    {
        int base = ((t >> 3) << 6) + (t & 7);
        #pragma unroll
        for (int j = 0; j < 8; ++j) v[j] = s[pad(base + (j << 3))];
        fht_regs<8>(v);
        #pragma unroll
        for (int j = 0; j < 8; ++j) s[pad(base + (j << 3))] = v[j];
    }
    __syncthreads();
    {
        int base = ((t >> 6) << 9) + (t & 63);
        #pragma unroll
        for (int j = 0; j < 8; ++j) v[j] = s[pad(base + (j << 6))];
        fht_regs<8>(v);
        #pragma unroll
        for (int j = 0; j < 8; ++j) s[pad(base + (j << 6))] = v[j];
    }
    __syncthreads();
    if (t < 512) {
        #pragma unroll
        for (int j = 0; j < 16; ++j) v[j] = s[pad(t + (j << 9))];
        fht_regs<16>(v);
        #pragma unroll
        for (int j = 0; j < 16; ++j) s[pad(t + (j << 9))] = v[j];
    }
    __syncthreads();
    const float sc = wsc_p[0] * 0.011048543456039806f;  // Wscale / sqrt(8192)
    for (int m = t; m < MF; m += 1024)
        out[(size_t)row * MF + m] = s[pad(m)] * sc * SU[m];
}

// ---------------------------------------------------------------------------
extern "C" void kernel_launch(void* const* d_in, const int* in_sizes, int n_in,
                              void* d_out, int out_size) {
    const float* x      = (const float*)d_in[0];
    const int*   Qidxs  = (const int*)  d_in[1];
    const int*   Qidxs2 = (const int*)  d_in[2];
    const float* cb1    = (const float*)d_in[3];
    const float* cb2    = (const float*)d_in[4];
    const float* SU     = (const float*)d_in[5];
    const float* SV     = (const float*)d_in[6];
    const float* Wsc    = (const float*)d_in[7];
    const float* irs    = (const float*)d_in[8];
    float* out = (float*)d_out;

    cudaFuncSetAttribute(k_gemm, cudaFuncAttributeMaxDynamicSharedMemorySize, SMEM_SZ);

    k_fht_x<<<TOK, 1024>>>(x, SV);
    k_gemm<<<dim3(MF / MTILE, SPLITS), 256, SMEM_SZ>>>(Qidxs, Qidxs2, cb1, cb2, irs);
    k_final<<<TOK, 1024>>>(out, SU, Wsc);
}

// round 6
// speedup vs baseline: 1.8234x; 1.0256x over previous
#include <cuda_runtime.h>
#include <cuda_fp16.h>
#include <cstdint>
#include <cstddef>

#define TOK 64
#define NF 8192
#define MF 8192
#define SPLITS 4
#define KSPLIT 2048        /* NF / SPLITS */
#define KTILE 128
#define CHUNKS 16          /* KSPLIT / KTILE */
#define MTILE 128

// ---- scratch (allocation-free rule: device globals) ----
__device__ __half g_xh[TOK * NF];                  // 1 MB  FHT'd activations fp16 [tok][k]
__device__ float  g_yp[(size_t)SPLITS * TOK * MF]; // 8 MB split-K partials

// ---- k_gemm dynamic smem layout (XOR-swizzled tiles, dup codebooks) ----
#define OFF_CB1  0                       /* cb1 copy0 @0, copy1 @4096          */
#define OFF_CB2  8192                    /* cb2 copy0 @8192, copy1 @12288      */
#define OFF_W0   16384                   /* W buf: 128 rows x 256B = 32 KB     */
#define OFF_W1   (OFF_W0 + 32768)
#define OFF_X0   (OFF_W1 + 32768)        /* X buf: 64 rows x 256B = 16 KB      */
#define OFF_X1   (OFF_X0 + 16384)
#define SMEM_SZ  (OFF_X1 + 16384)        /* 114688 B = 112 KB -> 2 CTAs/SM     */
#define OBPAD 132                        /* epilogue fp32 row stride           */

// swizzled byte offset of (row, 16B-seg) within a tile (256B rows, 16 segs)
#define SWZ(row, seg) (((row) << 8) + ((((seg) ^ ((row) & 7))) << 4))

// named barriers: ready[b] = 1+b, consumed[b] = 3+b
#define BAR_READY(b)    (1 + (b))
#define BAR_CONSUMED(b) (3 + (b))

__device__ __forceinline__ uint32_t smem_u32(const void* p) {
    return (uint32_t)__cvta_generic_to_shared(p);
}
__device__ __forceinline__ void bar_sync(int id) {
    asm volatile("bar.sync %0, 256;" :: "r"(id) : "memory");
}
__device__ __forceinline__ void bar_arrive(int id) {
    asm volatile("bar.arrive %0, 256;" :: "r"(id) : "memory");
}
__device__ __forceinline__ void cp_async16(uint32_t dst, const void* src) {
    asm volatile("cp.async.cg.shared.global [%0], [%1], 16;" :: "r"(dst), "l"(src) : "memory");
}

// ---------------------------------------------------------------------------
// register FHT helpers
// ---------------------------------------------------------------------------
template <int N>
__device__ __forceinline__ void fht_regs(float* v) {
    #pragma unroll
    for (int h = 1; h < N; h <<= 1)
        #pragma unroll
        for (int i = 0; i < N; ++i)
            if ((i & h) == 0) { float a = v[i], b = v[i + h]; v[i] = a + b; v[i + h] = a - b; }
}
__device__ __forceinline__ int pad(int i) { return i + (i >> 5); }

// ---------------------------------------------------------------------------
// Kernel 1: x_rht = FHT(x * SV) -> fp16   (register radix, 4 smem rounds)
// ---------------------------------------------------------------------------
__global__ void __launch_bounds__(1024) k_fht_x(const float* __restrict__ x,
                                                const float* __restrict__ SV) {
    __shared__ float s[NF + NF / 32];
    const int row = blockIdx.x, t = threadIdx.x;
    float v[16];
    {   // R1: contiguous 8, stages h=1,2,4
        const float4* xp = (const float4*)(x + (size_t)row * NF + t * 8);
        const float4* sp = (const float4*)(SV + t * 8);
        float4 a0 = xp[0], a1 = xp[1], b0 = sp[0], b1 = sp[1];
        v[0] = a0.x * b0.x; v[1] = a0.y * b0.y; v[2] = a0.z * b0.z; v[3] = a0.w * b0.w;
        v[4] = a1.x * b1.x; v[5] = a1.y * b1.y; v[6] = a1.z * b1.z; v[7] = a1.w * b1.w;
        fht_regs<8>(v);
        int base = t * 8;
        #pragma unroll
        for (int j = 0; j < 8; ++j) s[pad(base + j)] = v[j];
    }
    __syncthreads();
    {   // R2: stride 8
        int base = ((t >> 3) << 6) + (t & 7);
        #pragma unroll
        for (int j = 0; j < 8; ++j) v[j] = s[pad(base + (j << 3))];
        fht_regs<8>(v);
        #pragma unroll
        for (int j = 0; j < 8; ++j) s[pad(base + (j << 3))] = v[j];
    }
    __syncthreads();
    {   // R3: stride 64
        int base = ((t >> 6) << 9) + (t & 63);
        #pragma unroll
        for (int j = 0; j < 8; ++j) v[j] = s[pad(base + (j << 6))];
        fht_regs<8>(v);
        #pragma unroll
        for (int j = 0; j < 8; ++j) s[pad(base + (j << 6))] = v[j];
    }
    __syncthreads();
    if (t < 512) {  // R4: stride 512, radix-16
        #pragma unroll
        for (int j = 0; j < 16; ++j) v[j] = s[pad(t + (j << 9))];
        fht_regs<16>(v);
        #pragma unroll
        for (int j = 0; j < 16; ++j) s[pad(t + (j << 9))] = v[j];
    }
    __syncthreads();
    const float sc = 0.011048543456039806f;  // 1/sqrt(8192)
    __half2* dst = (__half2*)(g_xh + (size_t)row * NF);
    for (int i = t; i < NF / 2; i += 1024)
        dst[i] = __floats2half2_rn(s[pad(2 * i)] * sc, s[pad(2 * i + 1)] * sc);
}

// ---------------------------------------------------------------------------
// Kernel 2: warp-specialized dequant + HMMA GEMM (swizzled tiles)
//   warps 0-3: consumers (MMA, warp tile 32m x 64n)
//   warps 4-7: producers (decode W + cp.async X)
// ---------------------------------------------------------------------------
__global__ void __launch_bounds__(256, 2) k_gemm(const int*   __restrict__ Qidxs,
                                                 const int*   __restrict__ Qidxs2,
                                                 const float* __restrict__ cb1g,
                                                 const float* __restrict__ cb2g,
                                                 const float* __restrict__ irs_p) {
    extern __shared__ char smem[];
    const int t = threadIdx.x, w = t >> 5, lane = t & 31;
    const int m0 = blockIdx.x * MTILE, split = blockIdx.y;
    const uint32_t sb = smem_u32(smem);

    // ---- fp16 codebooks, 2 copies each (cb2 pre-scaled by inv_resid_scale) ----
    {
        const float irs = irs_p[0];
        const float4* p1 = (const float4*)(cb1g + t * 8);
        const float4* p2 = (const float4*)(cb2g + t * 8);
        float4 a0 = p1[0], a1 = p1[1], b0 = p2[0], b1 = p2[1];
        union { uint4 u; __half2 h[4]; } pk;
        pk.h[0] = __floats2half2_rn(a0.x, a0.y); pk.h[1] = __floats2half2_rn(a0.z, a0.w);
        pk.h[2] = __floats2half2_rn(a1.x, a1.y); pk.h[3] = __floats2half2_rn(a1.z, a1.w);
        ((uint4*)(smem + OFF_CB1))[t] = pk.u;
        ((uint4*)(smem + OFF_CB1 + 4096))[t] = pk.u;
        pk.h[0] = __floats2half2_rn(b0.x * irs, b0.y * irs);
        pk.h[1] = __floats2half2_rn(b0.z * irs, b0.w * irs);
        pk.h[2] = __floats2half2_rn(b1.x * irs, b1.y * irs);
        pk.h[3] = __floats2half2_rn(b1.z * irs, b1.w * irs);
        ((uint4*)(smem + OFF_CB2))[t] = pk.u;
        ((uint4*)(smem + OFF_CB2 + 4096))[t] = pk.u;
    }
    __syncthreads();   // codebooks visible to producer gathers

    float acc[2][8][4];   // consumer accumulators (32m x 64n)

    if (w < 4) {
        // ================= CONSUMER =================
        #pragma unroll
        for (int mi = 0; mi < 2; ++mi)
            #pragma unroll
            for (int nt = 0; nt < 8; ++nt)
                #pragma unroll
                for (int e = 0; e < 4; ++e) acc[mi][nt][e] = 0.f;

        for (int c = 0; c < CHUNKS; ++c) {
            const int b = c & 1;
            bar_sync(BAR_READY(b));
            const char* ws = smem + (b ? OFF_W1 : OFF_W0);
            const char* xs = smem + (b ? OFF_X1 : OFF_X0);
            #pragma unroll
            for (int kk = 0; kk < 8; ++kk) {
                uint32_t A[2][4], B[8][2];
                #pragma unroll
                for (int mi = 0; mi < 2; ++mi) {
                    int row = w * 32 + mi * 16 + (lane & 15);
                    int seg = kk * 2 + (lane >> 4);
                    uint32_t ad = smem_u32(ws + SWZ(row, seg));
                    asm volatile("ldmatrix.sync.aligned.m8n8.x4.shared.b16 {%0,%1,%2,%3}, [%4];"
                                 : "=r"(A[mi][0]), "=r"(A[mi][1]), "=r"(A[mi][2]), "=r"(A[mi][3])
                                 : "r"(ad));
                }
                #pragma unroll
                for (int g = 0; g < 4; ++g) {   // 2 token-tiles per x4
                    int row = g * 16 + (lane & 15);
                    int seg = kk * 2 + (lane >> 4);
                    uint32_t bd = smem_u32(xs + SWZ(row, seg));
                    uint32_t r0, r1, r2, r3;
                    asm volatile("ldmatrix.sync.aligned.m8n8.x4.shared.b16 {%0,%1,%2,%3}, [%4];"
                                 : "=r"(r0), "=r"(r1), "=r"(r2), "=r"(r3) : "r"(bd));
                    B[2 * g][0] = r0;     B[2 * g][1] = r2;     // tok 0-7 of pair
                    B[2 * g + 1][0] = r1; B[2 * g + 1][1] = r3; // tok 8-15
                }
                #pragma unroll
                for (int mi = 0; mi < 2; ++mi)
                    #pragma unroll
                    for (int nt = 0; nt < 8; ++nt)
                        asm volatile("mma.sync.aligned.m16n8k16.row.col.f32.f16.f16.f32 "
                                     "{%0,%1,%2,%3}, {%4,%5,%6,%7}, {%8,%9}, {%0,%1,%2,%3};"
                                     : "+f"(acc[mi][nt][0]), "+f"(acc[mi][nt][1]),
                                       "+f"(acc[mi][nt][2]), "+f"(acc[mi][nt][3])
                                     : "r"(A[mi][0]), "r"(A[mi][1]), "r"(A[mi][2]), "r"(A[mi][3]),
                                       "r"(B[nt][0]), "r"(B[nt][1]));
            }
            bar_arrive(BAR_CONSUMED(b));
        }
    } else {
        // ================= PRODUCER =================
        const int pt = t - 128;                  // 0..127 = W row within tile
        // duplicated-codebook gather base: lane parity picks the copy
        const uint4* cb1 = (const uint4*)(smem + OFF_CB1 + (lane & 1) * 4096);
        const uint4* cb2 = (const uint4*)(smem + OFF_CB2 + (lane & 1) * 4096);
        const int* q1base = Qidxs  + (size_t)(m0 + pt) * (NF / 8) + split * (KSPLIT / 8);
        const int* q2base = Qidxs2 + (size_t)(m0 + pt) * (NF / 8) + split * (KSPLIT / 8);

        int4 c1[4], c2[4], n1[4], n2[4];
        #pragma unroll
        for (int i = 0; i < 4; ++i) {            // prime chunk 0 indices
            c1[i] = *(const int4*)(q1base + i * 4);
            c2[i] = *(const int4*)(q2base + i * 4);
        }

        for (int c = 0; c < CHUNKS; ++c) {
            const int b = c & 1;
            if (c >= 2) bar_sync(BAR_CONSUMED(b));

            // stage X tile via cp.async into swizzled layout
            const int k0 = split * KSPLIT + c * KTILE;
            const uint32_t xb = sb + (b ? OFF_X1 : OFF_X0);
            #pragma unroll
            for (int i = 0; i < 8; ++i) {
                int idx = pt + 128 * i, tok = idx >> 4, seg = idx & 15;
                cp_async16(xb + SWZ(tok, seg),
                           g_xh + (size_t)tok * NF + k0 + seg * 8);
            }
            asm volatile("cp.async.commit_group;" ::: "memory");

            // prefetch next chunk's indices (hidden under decode below)
            if (c + 1 < CHUNKS) {
                #pragma unroll
                for (int i = 0; i < 4; ++i) {
                    n1[i] = *(const int4*)(q1base + (c + 1) * 16 + i * 4);
                    n2[i] = *(const int4*)(q2base + (c + 1) * 16 + i * 4);
                }
            }

            // decode this chunk's 16 groups for row pt into swizzled W
            {
                int q1[16] = {c1[0].x, c1[0].y, c1[0].z, c1[0].w,
                              c1[1].x, c1[1].y, c1[1].z, c1[1].w,
                              c1[2].x, c1[2].y, c1[2].z, c1[2].w,
                              c1[3].x, c1[3].y, c1[3].z, c1[3].w};
                int q2[16] = {c2[0].x, c2[0].y, c2[0].z, c2[0].w,
                              c2[1].x, c2[1].y, c2[1].z, c2[1].w,
                              c2[2].x, c2[2].y, c2[2].z, c2[2].w,
                              c2[3].x, c2[3].y, c2[3].z, c2[3].w};
                char* wb = smem + (b ? OFF_W1 : OFF_W0);
                const uint32_t rbase = pt << 8;
                const uint32_t rx = (pt & 7) << 4;
                #pragma unroll
                for (int j = 0; j < 16; ++j) {
                    uint4 v1 = cb1[q1[j]], v2 = cb2[q2[j]];
                    __half2* h1 = (__half2*)&v1;
                    const __half2* h2 = (const __half2*)&v2;
                    h1[0] = __hadd2(h1[0], h2[0]); h1[1] = __hadd2(h1[1], h2[1]);
                    h1[2] = __hadd2(h1[2], h2[2]); h1[3] = __hadd2(h1[3], h2[3]);
                    *(uint4*)(wb + (rbase + (((uint32_t)(j << 4)) ^ rx))) = v1;
                }
            }

            asm volatile("cp.async.wait_group 0;" ::: "memory");
            bar_arrive(BAR_READY(b));

            #pragma unroll
            for (int i = 0; i < 4; ++i) { c1[i] = n1[i]; c2[i] = n2[i]; }
        }
    }

    // ---- epilogue: consumer regs -> smem transpose [tok][m] ----
    float* ob = (float*)(smem + OFF_W0);    // 64 * OBPAD * 4 = 33792 B (W0+W1 dead)
    if (w < 4) {
        #pragma unroll
        for (int mi = 0; mi < 2; ++mi)
            #pragma unroll
            for (int nt = 0; nt < 8; ++nt) {
                int m = w * 32 + mi * 16 + (lane >> 2);
                int n = nt * 8 + (lane & 3) * 2;
                ob[n * OBPAD + m]           = acc[mi][nt][0];
                ob[(n + 1) * OBPAD + m]     = acc[mi][nt][1];
                ob[n * OBPAD + m + 8]       = acc[mi][nt][2];
                ob[(n + 1) * OBPAD + m + 8] = acc[mi][nt][3];
            }
    }
    __syncthreads();
    float* dst = g_yp + (size_t)split * TOK * MF;
    #pragma unroll
    for (int i = 0; i < 8; ++i) {
        int idx = t + 256 * i, tok = idx >> 5, seg = idx & 31;
        float4 val = *(const float4*)(ob + tok * OBPAD + seg * 4);
        *(float4*)(dst + (size_t)tok * MF + m0 + seg * 4) = val;
    }
}

// ---------------------------------------------------------------------------
// Kernel 3: reduce splits, FHT along m, apply Wscale & SU
// ---------------------------------------------------------------------------
__global__ void __launch_bounds__(1024) k_final(float* __restrict__ out,
                                                const float* __restrict__ SU,
                                                const float* __restrict__ wsc_p) {
    __shared__ float s[MF + MF / 32];
    const int row = blockIdx.x, t = threadIdx.x;
    float v[16];
    {   // load + split reduction + R1
        float4 a0 = {0, 0, 0, 0}, a1 = {0, 0, 0, 0};
        #pragma unroll
        for (int sp = 0; sp < SPLITS; ++sp) {
            const float4* p = (const float4*)(g_yp + ((size_t)sp * TOK + row) * MF + t * 8);
            float4 x0 = p[0], x1 = p[1];
            a0.x += x0.x; a0.y += x0.y; a0.z += x0.z; a0.w += x0.w;
            a1.x += x1.x; a1.y += x1.y; a1.z += x1.z; a1.w += x1.w;
        }
        v[0] = a0.x; v[1] = a0.y; v[2] = a0.z; v[3] = a0.w;
        v[4] = a1.x; v[5] = a1.y; v[6] = a1.z; v[7] = a1.w;
        fht_regs<8>(v);
        int base = t * 8;
        #pragma unroll
        for (int j = 0; j < 8; ++j) s[pad(base + j)] = v[j];
    }
    __syncthreads();
    {
        int base = ((t >> 3) << 6) + (t & 7);
        #pragma unroll
        for (int j = 0; j < 8; ++j) v[j] = s[pad(base + (j << 3))];
        fht_regs<8>(v);
        #pragma unroll
        for (int j = 0; j < 8; ++j) s[pad(base + (j << 3))] = v[j];
    }
    __syncthreads();
    {
        int base = ((t >> 6) << 9) + (t & 63);
        #pragma unroll
        for (int j = 0; j < 8; ++j) v[j] = s[pad(base + (j << 6))];
        fht_regs<8>(v);
        #pragma unroll
        for (int j = 0; j < 8; ++j) s[pad(base + (j << 6))] = v[j];
    }
    __syncthreads();
    if (t < 512) {
        #pragma unroll
        for (int j = 0; j < 16; ++j) v[j] = s[pad(t + (j << 9))];
        fht_regs<16>(v);
        #pragma unroll
        for (int j = 0; j < 16; ++j) s[pad(t + (j << 9))] = v[j];
    }
    __syncthreads();
    const float sc = wsc_p[0] * 0.011048543456039806f;  // Wscale / sqrt(8192)
    for (int m = t; m < MF; m += 1024)
        out[(size_t)row * MF + m] = s[pad(m)] * sc * SU[m];
}

// ---------------------------------------------------------------------------
extern "C" void kernel_launch(void* const* d_in, const int* in_sizes, int n_in,
                              void* d_out, int out_size) {
    const float* x      = (const float*)d_in[0];
    const int*   Qidxs  = (const int*)  d_in[1];
    const int*   Qidxs2 = (const int*)  d_in[2];
    const float* cb1    = (const float*)d_in[3];
    const float* cb2    = (const float*)d_in[4];
    const float* SU     = (const float*)d_in[5];
    const float* SV     = (const float*)d_in[6];
    const float* Wsc    = (const float*)d_in[7];
    const float* irs    = (const float*)d_in[8];
    float* out = (float*)d_out;

    cudaFuncSetAttribute(k_gemm, cudaFuncAttributeMaxDynamicSharedMemorySize, SMEM_SZ);

    k_fht_x<<<TOK, 1024>>>(x, SV);
    k_gemm<<<dim3(MF / MTILE, SPLITS), 256, SMEM_SZ>>>(Qidxs, Qidxs2, cb1, cb2, irs);
    k_final<<<TOK, 1024>>>(out, SU, Wsc);
}